// round 2
// baseline (speedup 1.0000x reference)
#include <cuda_runtime.h>

// Problem constants
#define TT 16384   // B*N tokens
#define DD 768
#define HH 3072
#define EE 8

// GEMM tile config
#define BM 128
#define BN 128
#define BK 8

// ---------------- scratch (device globals; no allocations allowed) ----------
__device__ int   g_cnt[EE];
__device__ int   g_tok[EE * TT];
__device__ float g_wt [EE * TT];
__device__ int   g_kidx[EE * TT];
// padded per-expert h buffer: worst case every token to one expert
__device__ float g_h[(size_t)EE * TT * HH];      // ~1.6 GB
__device__ float g_yp[(size_t)TT * 2 * DD];      // per-token, per-k partial y

// ---------------------------------------------------------------------------
__global__ void zero_cnt_kernel() {
    if (threadIdx.x < EE) g_cnt[threadIdx.x] = 0;
}

// Router: one warp per token. logits = x @ rw + rb, top-2, softmax, build lists.
__global__ __launch_bounds__(256) void router_kernel(
    const float* __restrict__ x,
    const float* __restrict__ rw,
    const float* __restrict__ rb)
{
    int gwarp = (blockIdx.x * blockDim.x + threadIdx.x) >> 5;
    int lane  = threadIdx.x & 31;
    if (gwarp >= TT) return;
    const float* xr = x + (size_t)gwarp * DD;

    float acc[EE];
#pragma unroll
    for (int e = 0; e < EE; e++) acc[e] = 0.f;

    for (int d = lane; d < DD; d += 32) {
        float xv = xr[d];
        const float4 w0 = *(const float4*)(rw + (size_t)d * EE);
        const float4 w1 = *(const float4*)(rw + (size_t)d * EE + 4);
        acc[0] += xv * w0.x; acc[1] += xv * w0.y;
        acc[2] += xv * w0.z; acc[3] += xv * w0.w;
        acc[4] += xv * w1.x; acc[5] += xv * w1.y;
        acc[6] += xv * w1.z; acc[7] += xv * w1.w;
    }
#pragma unroll
    for (int off = 16; off; off >>= 1) {
#pragma unroll
        for (int e = 0; e < EE; e++)
            acc[e] += __shfl_down_sync(0xffffffffu, acc[e], off);
    }
    if (lane == 0) {
        float lg[EE];
#pragma unroll
        for (int e = 0; e < EE; e++) lg[e] = acc[e] + rb[e];
        // top-2 (first occurrence on ties, like jax top_k)
        int i0 = 0; float v0 = lg[0];
#pragma unroll
        for (int e = 1; e < EE; e++) if (lg[e] > v0) { v0 = lg[e]; i0 = e; }
        int i1 = -1; float v1 = -3.4e38f;
#pragma unroll
        for (int e = 0; e < EE; e++) {
            if (e == i0) continue;
            if (lg[e] > v1) { v1 = lg[e]; i1 = e; }
        }
        float e1 = __expf(v1 - v0);
        float w0 = 1.f / (1.f + e1);
        float w1 = e1 * w0;

        int s0 = atomicAdd(&g_cnt[i0], 1);
        g_tok[i0 * TT + s0] = gwarp;
        g_wt [i0 * TT + s0] = w0;
        g_kidx[i0 * TT + s0] = 0;

        int s1 = atomicAdd(&g_cnt[i1], 1);
        g_tok[i1 * TT + s1] = gwarp;
        g_wt [i1 * TT + s1] = w1;
        g_kidx[i1 * TT + s1] = 1;
    }
}

__device__ __forceinline__ float gelu_exact(float v) {
    return 0.5f * v * (1.f + erff(v * 0.70710678118654752440f));
}

// GEMM1: h[slot, n] = gelu( x[tok[slot], :] @ w1[e][:, n] + b1[e][n] )
__global__ __launch_bounds__(256, 2) void gemm1_kernel(
    const float* __restrict__ x,
    const float* __restrict__ w1,
    const float* __restrict__ b1)
{
    int e   = blockIdx.z;
    int cnt = g_cnt[e];
    int m0  = blockIdx.y * BM;
    if (m0 >= cnt) return;
    int n0  = blockIdx.x * BN;
    const float* Bp = w1 + (size_t)e * DD * HH;

    __shared__ float As[BK][BM];
    __shared__ float Bs[BK][BN];

    int tid  = threadIdx.x;
    int arow = tid >> 1;
    int acol = (tid & 1) << 2;
    int brow = tid >> 5;
    int bcol = (tid & 31) << 2;
    int tx   = tid & 15, ty = tid >> 4;

    const float* aptr = nullptr;
    {
        int gr = m0 + arow;
        if (gr < cnt) aptr = x + (size_t)g_tok[e * TT + gr] * DD + acol;
    }
    const float* bptr = Bp + (size_t)brow * HH + n0 + bcol;

    float4 pa = aptr ? *(const float4*)aptr : make_float4(0.f, 0.f, 0.f, 0.f);
    float4 pb = *(const float4*)bptr;

    float acc[8][8];
#pragma unroll
    for (int i = 0; i < 8; i++)
#pragma unroll
        for (int j = 0; j < 8; j++) acc[i][j] = 0.f;

    for (int k0 = 0; k0 < DD; k0 += BK) {
        As[acol + 0][arow] = pa.x; As[acol + 1][arow] = pa.y;
        As[acol + 2][arow] = pa.z; As[acol + 3][arow] = pa.w;
        *(float4*)&Bs[brow][bcol] = pb;
        __syncthreads();
        if (k0 + BK < DD) {
            pa = aptr ? *(const float4*)(aptr + k0 + BK)
                      : make_float4(0.f, 0.f, 0.f, 0.f);
            pb = *(const float4*)(bptr + (size_t)(k0 + BK) * HH);
        }
#pragma unroll
        for (int kk = 0; kk < BK; kk++) {
            float a[8], b[8];
            *(float4*)&a[0] = *(const float4*)&As[kk][ty * 4];
            *(float4*)&a[4] = *(const float4*)&As[kk][64 + ty * 4];
            *(float4*)&b[0] = *(const float4*)&Bs[kk][tx * 4];
            *(float4*)&b[4] = *(const float4*)&Bs[kk][64 + tx * 4];
#pragma unroll
            for (int i = 0; i < 8; i++)
#pragma unroll
                for (int j = 0; j < 8; j++)
                    acc[i][j] = fmaf(a[i], b[j], acc[i][j]);
        }
        __syncthreads();
    }

    const float* b1e = b1 + e * HH + n0;
    float4 bv0 = *(const float4*)(b1e + tx * 4);
    float4 bv1 = *(const float4*)(b1e + 64 + tx * 4);
    float bb[8] = {bv0.x, bv0.y, bv0.z, bv0.w, bv1.x, bv1.y, bv1.z, bv1.w};

#pragma unroll
    for (int i = 0; i < 8; i++) {
        int r  = (i < 4) ? (ty * 4 + i) : (64 + ty * 4 + i - 4);
        int gr = m0 + r;
        if (gr >= cnt) continue;
        float* hrow = g_h + ((size_t)e * TT + gr) * HH + n0;
        float4 o0, o1;
        o0.x = gelu_exact(acc[i][0] + bb[0]);
        o0.y = gelu_exact(acc[i][1] + bb[1]);
        o0.z = gelu_exact(acc[i][2] + bb[2]);
        o0.w = gelu_exact(acc[i][3] + bb[3]);
        o1.x = gelu_exact(acc[i][4] + bb[4]);
        o1.y = gelu_exact(acc[i][5] + bb[5]);
        o1.z = gelu_exact(acc[i][6] + bb[6]);
        o1.w = gelu_exact(acc[i][7] + bb[7]);
        *(float4*)(hrow + tx * 4)      = o0;
        *(float4*)(hrow + 64 + tx * 4) = o1;
    }
}

// GEMM2: y_partial[tok, kidx, n] = ( h[slot,:] @ w2[e][:, n] + b2[e][n] ) * wt
__global__ __launch_bounds__(256, 2) void gemm2_kernel(
    const float* __restrict__ w2,
    const float* __restrict__ b2)
{
    int e   = blockIdx.z;
    int cnt = g_cnt[e];
    int m0  = blockIdx.y * BM;
    if (m0 >= cnt) return;
    int n0  = blockIdx.x * BN;
    const float* Bp = w2 + (size_t)e * HH * DD;

    __shared__ float As[BK][BM];
    __shared__ float Bs[BK][BN];

    int tid  = threadIdx.x;
    int arow = tid >> 1;
    int acol = (tid & 1) << 2;
    int brow = tid >> 5;
    int bcol = (tid & 31) << 2;
    int tx   = tid & 15, ty = tid >> 4;

    const float* aptr = nullptr;
    {
        int gr = m0 + arow;
        if (gr < cnt) aptr = g_h + ((size_t)e * TT + gr) * HH + acol;
    }
    const float* bptr = Bp + (size_t)brow * DD + n0 + bcol;

    float4 pa = aptr ? *(const float4*)aptr : make_float4(0.f, 0.f, 0.f, 0.f);
    float4 pb = *(const float4*)bptr;

    float acc[8][8];
#pragma unroll
    for (int i = 0; i < 8; i++)
#pragma unroll
        for (int j = 0; j < 8; j++) acc[i][j] = 0.f;

    for (int k0 = 0; k0 < HH; k0 += BK) {
        As[acol + 0][arow] = pa.x; As[acol + 1][arow] = pa.y;
        As[acol + 2][arow] = pa.z; As[acol + 3][arow] = pa.w;
        *(float4*)&Bs[brow][bcol] = pb;
        __syncthreads();
        if (k0 + BK < HH) {
            pa = aptr ? *(const float4*)(aptr + k0 + BK)
                      : make_float4(0.f, 0.f, 0.f, 0.f);
            pb = *(const float4*)(bptr + (size_t)(k0 + BK) * DD);
        }
#pragma unroll
        for (int kk = 0; kk < BK; kk++) {
            float a[8], b[8];
            *(float4*)&a[0] = *(const float4*)&As[kk][ty * 4];
            *(float4*)&a[4] = *(const float4*)&As[kk][64 + ty * 4];
            *(float4*)&b[0] = *(const float4*)&Bs[kk][tx * 4];
            *(float4*)&b[4] = *(const float4*)&Bs[kk][64 + tx * 4];
#pragma unroll
            for (int i = 0; i < 8; i++)
#pragma unroll
                for (int j = 0; j < 8; j++)
                    acc[i][j] = fmaf(a[i], b[j], acc[i][j]);
        }
        __syncthreads();
    }

    const float* b2e = b2 + e * DD + n0;
    float4 bv0 = *(const float4*)(b2e + tx * 4);
    float4 bv1 = *(const float4*)(b2e + 64 + tx * 4);
    float bb[8] = {bv0.x, bv0.y, bv0.z, bv0.w, bv1.x, bv1.y, bv1.z, bv1.w};

#pragma unroll
    for (int i = 0; i < 8; i++) {
        int r  = (i < 4) ? (ty * 4 + i) : (64 + ty * 4 + i - 4);
        int gr = m0 + r;
        if (gr >= cnt) continue;
        int   tok = g_tok[e * TT + gr];
        float wt  = g_wt [e * TT + gr];
        int   kx  = g_kidx[e * TT + gr];
        float* orow = g_yp + ((size_t)tok * 2 + kx) * DD + n0;
        float4 o0, o1;
        o0.x = (acc[i][0] + bb[0]) * wt;
        o0.y = (acc[i][1] + bb[1]) * wt;
        o0.z = (acc[i][2] + bb[2]) * wt;
        o0.w = (acc[i][3] + bb[3]) * wt;
        o1.x = (acc[i][4] + bb[4]) * wt;
        o1.y = (acc[i][5] + bb[5]) * wt;
        o1.z = (acc[i][6] + bb[6]) * wt;
        o1.w = (acc[i][7] + bb[7]) * wt;
        *(float4*)(orow + tx * 4)      = o0;
        *(float4*)(orow + 64 + tx * 4) = o1;
    }
}

// Residual + LayerNorm. One block (256 threads) per token; 3 elems/thread.
__device__ __forceinline__ float block_sum256(float v) {
    __shared__ float sh[8];
    int lane = threadIdx.x & 31, w = threadIdx.x >> 5;
#pragma unroll
    for (int o = 16; o; o >>= 1) v += __shfl_down_sync(0xffffffffu, v, o);
    if (lane == 0) sh[w] = v;
    __syncthreads();
    if (threadIdx.x == 0) {
        float s = 0.f;
#pragma unroll
        for (int i = 0; i < 8; i++) s += sh[i];
        sh[0] = s;
    }
    __syncthreads();
    float r = sh[0];
    __syncthreads();
    return r;
}

__global__ __launch_bounds__(256) void ln_kernel(
    const float* __restrict__ x,
    const float* __restrict__ gamma,
    const float* __restrict__ beta,
    float* __restrict__ out)
{
    int t = blockIdx.x;
    const float* xr = x   + (size_t)t * DD;
    const float* p0 = g_yp + (size_t)t * 2 * DD;
    const float* p1 = p0 + DD;

    float v[3];
    float s = 0.f;
#pragma unroll
    for (int i = 0; i < 3; i++) {
        int d = threadIdx.x + i * 256;
        v[i] = xr[d] + p0[d] + p1[d];
        s += v[i];
    }
    s = block_sum256(s);
    float mu = s * (1.f / (float)DD);
    float q = 0.f;
#pragma unroll
    for (int i = 0; i < 3; i++) { float dl = v[i] - mu; q += dl * dl; }
    q = block_sum256(q);
    float rstd = rsqrtf(q * (1.f / (float)DD) + 1e-5f);
#pragma unroll
    for (int i = 0; i < 3; i++) {
        int d = threadIdx.x + i * 256;
        out[(size_t)t * DD + d] = (v[i] - mu) * rstd * gamma[d] + beta[d];
    }
}

// ---------------------------------------------------------------------------
extern "C" void kernel_launch(void* const* d_in, const int* in_sizes, int n_in,
                              void* d_out, int out_size)
{
    (void)in_sizes; (void)n_in; (void)out_size;
    const float* x    = (const float*)d_in[0];
    const float* rw   = (const float*)d_in[1];
    const float* rb   = (const float*)d_in[2];
    const float* w1   = (const float*)d_in[3];
    const float* b1   = (const float*)d_in[4];
    const float* w2   = (const float*)d_in[5];
    const float* b2   = (const float*)d_in[6];
    const float* gam  = (const float*)d_in[7];
    const float* bet  = (const float*)d_in[8];
    float* out = (float*)d_out;

    zero_cnt_kernel<<<1, 32>>>();
    router_kernel<<<TT / 8, 256>>>(x, rw, rb);                    // 8 warps/block
    gemm1_kernel<<<dim3(HH / BN, TT / BM, EE), 256>>>(x, w1, b1);
    gemm2_kernel<<<dim3(DD / BN, TT / BM, EE), 256>>>(w2, b2);
    ln_kernel<<<TT, 256>>>(x, gam, bet, out);
}

// round 4
// speedup vs baseline: 1.7588x; 1.7588x over previous
#include <cuda_runtime.h>
#include <cuda_bf16.h>
#include <cstdint>

#define TT 16384
#define DD 768
#define HH 3072
#define EE 8
#define HPAD (TT + 128)

// ---------------- scratch globals ------------------------------------------
__device__ int   g_cnt[EE];
__device__ int   g_tok[EE * TT];
__device__ float g_wt [EE * TT];
__device__ int   g_kidx[EE * TT];
__device__ __nv_bfloat16 g_x_hi[(size_t)TT * DD];
__device__ __nv_bfloat16 g_x_lo[(size_t)TT * DD];
__device__ __nv_bfloat16 g_w1t_hi[(size_t)EE * HH * DD];  // [E][H][D] K-major
__device__ __nv_bfloat16 g_w1t_lo[(size_t)EE * HH * DD];
__device__ __nv_bfloat16 g_w2t_hi[(size_t)EE * DD * HH];  // [E][D][H] K-major
__device__ __nv_bfloat16 g_w2t_lo[(size_t)EE * DD * HH];
__device__ __nv_bfloat16 g_h_hi[(size_t)EE * HPAD * HH];
__device__ __nv_bfloat16 g_h_lo[(size_t)EE * HPAD * HH];
__device__ float g_yp[(size_t)TT * 2 * DD];

// ---------------- PTX helpers (base ISA only; no tcgen05) -------------------
__device__ __forceinline__ uint32_t smem_u32(const void* p) {
    uint32_t a;
    asm("{ .reg .u64 t; cvta.to.shared.u64 t, %1; cvt.u32.u64 %0, t; }"
        : "=r"(a) : "l"(p));
    return a;
}
__device__ __forceinline__ void cpa16(uint32_t dst, const void* src) {
    asm volatile("cp.async.cg.shared.global [%0], [%1], 16;" :: "r"(dst), "l"(src));
}
__device__ __forceinline__ void cpa_commit() {
    asm volatile("cp.async.commit_group;" ::: "memory");
}
template<int N> __device__ __forceinline__ void cpa_wait() {
    asm volatile("cp.async.wait_group %0;" :: "n"(N) : "memory");
}
__device__ __forceinline__ void ldsm4(uint32_t* r, uint32_t addr) {
    asm volatile("ldmatrix.sync.aligned.m8n8.x4.shared.b16 {%0,%1,%2,%3}, [%4];"
                 : "=r"(r[0]), "=r"(r[1]), "=r"(r[2]), "=r"(r[3]) : "r"(addr));
}
__device__ __forceinline__ void mma16816(float* c, const uint32_t* a, const uint32_t* b) {
    asm volatile(
        "mma.sync.aligned.m16n8k16.row.col.f32.bf16.bf16.f32 "
        "{%0,%1,%2,%3}, {%4,%5,%6,%7}, {%8,%9}, {%0,%1,%2,%3};"
        : "+f"(c[0]), "+f"(c[1]), "+f"(c[2]), "+f"(c[3])
        : "r"(a[0]), "r"(a[1]), "r"(a[2]), "r"(a[3]), "r"(b[0]), "r"(b[1]));
}
__device__ __forceinline__ uint32_t swz(uint32_t off) {
    return off ^ ((off >> 3) & 0x70);
}
__device__ __forceinline__ float gelu_exact(float v) {
    return 0.5f * v * (1.f + erff(v * 0.70710678118654752440f));
}

// ---------------- small kernels --------------------------------------------
__global__ void zero_cnt_kernel() {
    if (threadIdx.x < EE) g_cnt[threadIdx.x] = 0;
}

__global__ __launch_bounds__(256) void convert_x_kernel(const float* __restrict__ x) {
    size_t i = ((size_t)blockIdx.x * 256 + threadIdx.x) * 4;
    float4 v = *(const float4*)(x + i);
    __nv_bfloat16 h0 = __float2bfloat16(v.x), h1 = __float2bfloat16(v.y);
    __nv_bfloat16 h2 = __float2bfloat16(v.z), h3 = __float2bfloat16(v.w);
    __nv_bfloat16 l0 = __float2bfloat16(v.x - __bfloat162float(h0));
    __nv_bfloat16 l1 = __float2bfloat16(v.y - __bfloat162float(h1));
    __nv_bfloat16 l2 = __float2bfloat16(v.z - __bfloat162float(h2));
    __nv_bfloat16 l3 = __float2bfloat16(v.w - __bfloat162float(h3));
    __nv_bfloat162 hp0; hp0.x = h0; hp0.y = h1;
    __nv_bfloat162 hp1; hp1.x = h2; hp1.y = h3;
    __nv_bfloat162 lp0; lp0.x = l0; lp0.y = l1;
    __nv_bfloat162 lp1; lp1.x = l2; lp1.y = l3;
    uint2 hh, ll;
    hh.x = *(uint32_t*)&hp0; hh.y = *(uint32_t*)&hp1;
    ll.x = *(uint32_t*)&lp0; ll.y = *(uint32_t*)&lp1;
    *(uint2*)(g_x_hi + i) = hh;
    *(uint2*)(g_x_lo + i) = ll;
}

// which=0: w1 [E][D][H] -> [E][H][D]; which=1: w2 [E][H][D] -> [E][D][H]
__global__ __launch_bounds__(256) void transpose_split_kernel(
    const float* __restrict__ in, int which)
{
    int R = which ? HH : DD;
    int C = which ? DD : HH;
    __nv_bfloat16* ohi = which ? g_w2t_hi : g_w1t_hi;
    __nv_bfloat16* olo = which ? g_w2t_lo : g_w1t_lo;
    __shared__ float tile[32][33];
    int e  = blockIdx.z;
    int r0 = blockIdx.y * 32, c0 = blockIdx.x * 32;
    const float* src = in + (size_t)e * R * C;
    for (int i = threadIdx.y; i < 32; i += 8)
        tile[i][threadIdx.x] = src[(size_t)(r0 + i) * C + c0 + threadIdx.x];
    __syncthreads();
    __nv_bfloat16* dh = ohi + (size_t)e * R * C;
    __nv_bfloat16* dl = olo + (size_t)e * R * C;
    for (int i = threadIdx.y; i < 32; i += 8) {
        float v = tile[threadIdx.x][i];
        size_t o = (size_t)(c0 + i) * R + r0 + threadIdx.x;
        __nv_bfloat16 h = __float2bfloat16(v);
        dh[o] = h;
        dl[o] = __float2bfloat16(v - __bfloat162float(h));
    }
}

__global__ __launch_bounds__(256) void router_kernel(
    const float* __restrict__ x,
    const float* __restrict__ rw,
    const float* __restrict__ rb)
{
    int gwarp = (blockIdx.x * blockDim.x + threadIdx.x) >> 5;
    int lane  = threadIdx.x & 31;
    if (gwarp >= TT) return;
    const float* xr = x + (size_t)gwarp * DD;

    float acc[EE];
#pragma unroll
    for (int e = 0; e < EE; e++) acc[e] = 0.f;
    for (int d = lane; d < DD; d += 32) {
        float xv = xr[d];
        const float4 w0 = *(const float4*)(rw + (size_t)d * EE);
        const float4 w1 = *(const float4*)(rw + (size_t)d * EE + 4);
        acc[0] += xv * w0.x; acc[1] += xv * w0.y;
        acc[2] += xv * w0.z; acc[3] += xv * w0.w;
        acc[4] += xv * w1.x; acc[5] += xv * w1.y;
        acc[6] += xv * w1.z; acc[7] += xv * w1.w;
    }
#pragma unroll
    for (int off = 16; off; off >>= 1)
#pragma unroll
        for (int e = 0; e < EE; e++)
            acc[e] += __shfl_down_sync(0xffffffffu, acc[e], off);
    if (lane == 0) {
        float lg[EE];
#pragma unroll
        for (int e = 0; e < EE; e++) lg[e] = acc[e] + rb[e];
        int i0 = 0; float v0 = lg[0];
#pragma unroll
        for (int e = 1; e < EE; e++) if (lg[e] > v0) { v0 = lg[e]; i0 = e; }
        int i1 = -1; float v1 = -3.4e38f;
#pragma unroll
        for (int e = 0; e < EE; e++) {
            if (e == i0) continue;
            if (lg[e] > v1) { v1 = lg[e]; i1 = e; }
        }
        float e1 = __expf(v1 - v0);
        float w0 = 1.f / (1.f + e1);
        float w1 = e1 * w0;
        int s0 = atomicAdd(&g_cnt[i0], 1);
        g_tok[i0 * TT + s0] = gwarp; g_wt[i0 * TT + s0] = w0; g_kidx[i0 * TT + s0] = 0;
        int s1 = atomicAdd(&g_cnt[i1], 1);
        g_tok[i1 * TT + s1] = gwarp; g_wt[i1 * TT + s1] = w1; g_kidx[i1 * TT + s1] = 1;
    }
}

// ---------------- bf16x3 GEMM via mma.sync (base ISA, tensor pipe) ----------
// D[m,n] = sum_k A[m,k]*B[n,k].  CTA: 128x128 tile, 256 thr (8 warps, 4m x 2n),
// warp tile 32m x 64n. K-chunk 64, SW128 K-major smem, cp.async 3-stage.
template<int K_TOT, bool G1>
__global__ void __launch_bounds__(256, 1) gemm_tc_kernel(const float* __restrict__ bias)
{
    constexpr int NK    = K_TOT / 64;
    constexpr int AB    = 128 * 128;      // 16 KB per matrix per stage
    constexpr int STAGE = 4 * AB;         // Ah, Al, Bh, Bl
    constexpr int NTOT  = G1 ? HH : DD;

    int e   = blockIdx.z;
    int cnt = g_cnt[e];
    int m0  = blockIdx.y * 128;
    if (m0 >= cnt) return;
    int n0  = blockIdx.x * 128;

    extern __shared__ char dynsm[];
    uint32_t dsm = (smem_u32(dynsm) + 1023u) & ~1023u;

    int tid = threadIdx.x, wid = tid >> 5, lane = tid & 31;
    int warp_m = (wid & 3) * 32;
    int warp_n = (wid >> 2) * 64;

    // per-thread load source rows
    const __nv_bfloat16 *arow_hi, *arow_lo;
    {
        int r = tid >> 1;
        if (G1) {
            int gr = m0 + r; if (gr > cnt - 1) gr = cnt - 1;
            int t = g_tok[e * TT + gr];
            arow_hi = g_x_hi + (size_t)t * DD;
            arow_lo = g_x_lo + (size_t)t * DD;
        } else {
            size_t slot = (size_t)e * HPAD + m0 + r;
            arow_hi = g_h_hi + slot * HH;
            arow_lo = g_h_lo + slot * HH;
        }
    }
    const __nv_bfloat16* brow_hi = (G1 ? g_w1t_hi : g_w2t_hi) +
        ((size_t)e * NTOT + n0 + (tid >> 1)) * (size_t)K_TOT;
    const __nv_bfloat16* brow_lo = (G1 ? g_w1t_lo : g_w2t_lo) +
        ((size_t)e * NTOT + n0 + (tid >> 1)) * (size_t)K_TOT;

    int lrow = tid >> 1;
    int lseg = (tid & 1) * 4;

    auto load_stage = [&](int s, int k0) {
        uint32_t st = dsm + s * STAGE;
#pragma unroll
        for (int q = 0; q < 4; q++) {
            uint32_t off = swz((uint32_t)(lrow * 128 + (lseg + q) * 16));
            const int koff = (lseg + q) * 8;
            cpa16(st + off,          arow_hi + k0 + koff);
            cpa16(st + AB + off,     arow_lo + k0 + koff);
            cpa16(st + 2 * AB + off, brow_hi + k0 + koff);
            cpa16(st + 3 * AB + off, brow_lo + k0 + koff);
        }
        cpa_commit();
    };

    float acc[2][8][4];
#pragma unroll
    for (int i = 0; i < 2; i++)
#pragma unroll
        for (int j = 0; j < 8; j++)
#pragma unroll
            for (int q = 0; q < 4; q++) acc[i][j][q] = 0.f;

    // ldmatrix per-lane address offsets (within tile, before swizzle)
    int a_r  = (lane & 7) + ((lane >> 3) & 1) * 8;   // row within 16
    int a_c  = (lane >> 4) * 16;                     // byte col 0/16
    int b_r  = (lane & 7) + (lane >> 4) * 8;
    int b_c  = ((lane >> 3) & 1) * 16;

    load_stage(0, 0);
    load_stage(1, 64);

    for (int i = 0; i < NK; i++) {
        __syncthreads();                       // all warps done with chunk i-1
        if (i + 2 < NK) load_stage((i + 2) % 3, (i + 2) * 64);
        if (i < NK - 2)       cpa_wait<2>();
        else if (i == NK - 2) cpa_wait<1>();
        else                  cpa_wait<0>();
        __syncthreads();

        uint32_t st = dsm + (i % 3) * STAGE;
#pragma unroll
        for (int kk = 0; kk < 4; kk++) {
            int c0 = kk * 32;
            uint32_t Ah[2][4], Al[2][4], Bh[8][2], Bl[8][2];
#pragma unroll
            for (int mf = 0; mf < 2; mf++) {
                int row = warp_m + mf * 16 + a_r;
                uint32_t off = swz((uint32_t)(row * 128 + c0 + a_c));
                ldsm4(Ah[mf], st + off);
                ldsm4(Al[mf], st + AB + off);
            }
#pragma unroll
            for (int np = 0; np < 4; np++) {
                int row = warp_n + np * 16 + b_r;
                uint32_t off = swz((uint32_t)(row * 128 + c0 + b_c));
                uint32_t r4[4];
                ldsm4(r4, st + 2 * AB + off);
                Bh[2 * np][0] = r4[0]; Bh[2 * np][1] = r4[1];
                Bh[2 * np + 1][0] = r4[2]; Bh[2 * np + 1][1] = r4[3];
                ldsm4(r4, st + 3 * AB + off);
                Bl[2 * np][0] = r4[0]; Bl[2 * np][1] = r4[1];
                Bl[2 * np + 1][0] = r4[2]; Bl[2 * np + 1][1] = r4[3];
            }
#pragma unroll
            for (int mf = 0; mf < 2; mf++)
#pragma unroll
                for (int nf = 0; nf < 8; nf++) {
                    mma16816(acc[mf][nf], Ah[mf], Bh[nf]);
                    mma16816(acc[mf][nf], Ah[mf], Bl[nf]);
                    mma16816(acc[mf][nf], Al[mf], Bh[nf]);
                }
        }
    }

    // ---------------- epilogue ----------------
    int lane4 = lane >> 2;
    int lcol  = (lane & 3) * 2;

#pragma unroll
    for (int mf = 0; mf < 2; mf++) {
#pragma unroll
        for (int h = 0; h < 2; h++) {
            int gr = m0 + warp_m + mf * 16 + h * 8 + lane4;
            if (gr >= cnt) continue;
            if (G1) {
                __nv_bfloat16* oh = g_h_hi + ((size_t)e * HPAD + gr) * HH;
                __nv_bfloat16* ol = g_h_lo + ((size_t)e * HPAD + gr) * HH;
                const float* bp = bias + (size_t)e * NTOT;
#pragma unroll
                for (int nf = 0; nf < 8; nf++) {
                    int n = n0 + warp_n + nf * 8 + lcol;
                    float v0 = gelu_exact(acc[mf][nf][h * 2 + 0] + bp[n]);
                    float v1 = gelu_exact(acc[mf][nf][h * 2 + 1] + bp[n + 1]);
                    __nv_bfloat16 h0 = __float2bfloat16(v0);
                    __nv_bfloat16 h1 = __float2bfloat16(v1);
                    __nv_bfloat16 l0 = __float2bfloat16(v0 - __bfloat162float(h0));
                    __nv_bfloat16 l1 = __float2bfloat16(v1 - __bfloat162float(h1));
                    __nv_bfloat162 hp; hp.x = h0; hp.y = h1;
                    __nv_bfloat162 lp; lp.x = l0; lp.y = l1;
                    *(uint32_t*)&oh[n] = *(uint32_t*)&hp;
                    *(uint32_t*)&ol[n] = *(uint32_t*)&lp;
                }
            } else {
                int idx = e * TT + gr;
                int   tok = g_tok[idx];
                float wt  = g_wt[idx];
                int   kx  = g_kidx[idx];
                float* orow = g_yp + ((size_t)tok * 2 + kx) * DD;
                const float* bp = bias + (size_t)e * NTOT;
#pragma unroll
                for (int nf = 0; nf < 8; nf++) {
                    int n = n0 + warp_n + nf * 8 + lcol;
                    float2 o;
                    o.x = (acc[mf][nf][h * 2 + 0] + bp[n])     * wt;
                    o.y = (acc[mf][nf][h * 2 + 1] + bp[n + 1]) * wt;
                    *(float2*)(orow + n) = o;
                }
            }
        }
    }
}

// ---------------- residual + LayerNorm --------------------------------------
__device__ __forceinline__ float block_sum256(float v) {
    __shared__ float sh[8];
    int lane = threadIdx.x & 31, w = threadIdx.x >> 5;
#pragma unroll
    for (int o = 16; o; o >>= 1) v += __shfl_down_sync(0xffffffffu, v, o);
    if (lane == 0) sh[w] = v;
    __syncthreads();
    if (threadIdx.x == 0) {
        float s = 0.f;
#pragma unroll
        for (int i = 0; i < 8; i++) s += sh[i];
        sh[0] = s;
    }
    __syncthreads();
    float r = sh[0];
    __syncthreads();
    return r;
}

__global__ __launch_bounds__(256) void ln_kernel(
    const float* __restrict__ x,
    const float* __restrict__ gamma,
    const float* __restrict__ beta,
    float* __restrict__ out)
{
    int t = blockIdx.x;
    const float* xr = x + (size_t)t * DD;
    const float* p0 = g_yp + (size_t)t * 2 * DD;
    const float* p1 = p0 + DD;

    float v[3];
    float s = 0.f;
#pragma unroll
    for (int i = 0; i < 3; i++) {
        int d = threadIdx.x + i * 256;
        v[i] = xr[d] + p0[d] + p1[d];
        s += v[i];
    }
    s = block_sum256(s);
    float mu = s * (1.f / (float)DD);
    float q = 0.f;
#pragma unroll
    for (int i = 0; i < 3; i++) { float dl = v[i] - mu; q += dl * dl; }
    q = block_sum256(q);
    float rstd = rsqrtf(q * (1.f / (float)DD) + 1e-5f);
#pragma unroll
    for (int i = 0; i < 3; i++) {
        int d = threadIdx.x + i * 256;
        out[(size_t)t * DD + d] = (v[i] - mu) * rstd * gamma[d] + beta[d];
    }
}

// ---------------------------------------------------------------------------
extern "C" void kernel_launch(void* const* d_in, const int* in_sizes, int n_in,
                              void* d_out, int out_size)
{
    (void)in_sizes; (void)n_in; (void)out_size;
    const float* x   = (const float*)d_in[0];
    const float* rw  = (const float*)d_in[1];
    const float* rb  = (const float*)d_in[2];
    const float* w1  = (const float*)d_in[3];
    const float* b1  = (const float*)d_in[4];
    const float* w2  = (const float*)d_in[5];
    const float* b2  = (const float*)d_in[6];
    const float* gam = (const float*)d_in[7];
    const float* bet = (const float*)d_in[8];
    float* out = (float*)d_out;

    const int SMEM_SZ = 3 * 4 * 128 * 128 + 1024;   // 3 stages x 64KB + pad
    cudaFuncSetAttribute(gemm_tc_kernel<DD, true>,
                         cudaFuncAttributeMaxDynamicSharedMemorySize, SMEM_SZ);
    cudaFuncSetAttribute(gemm_tc_kernel<HH, false>,
                         cudaFuncAttributeMaxDynamicSharedMemorySize, SMEM_SZ);

    zero_cnt_kernel<<<1, 32>>>();
    router_kernel<<<TT / 8, 256>>>(x, rw, rb);
    convert_x_kernel<<<(TT * DD) / (256 * 4), 256>>>(x);
    transpose_split_kernel<<<dim3(HH / 32, DD / 32, EE), dim3(32, 8)>>>(w1, 0);
    transpose_split_kernel<<<dim3(DD / 32, HH / 32, EE), dim3(32, 8)>>>(w2, 1);
    gemm_tc_kernel<DD, true><<<dim3(HH / 128, TT / 128, EE), 256, SMEM_SZ>>>(b1);
    gemm_tc_kernel<HH, false><<<dim3(DD / 128, TT / 128, EE), 256, SMEM_SZ>>>(b2);
    ln_kernel<<<TT, 256>>>(x, gam, bet, out);
}

// round 5
// speedup vs baseline: 4.2874x; 2.4377x over previous
#include <cuda_runtime.h>
#include <cuda_fp16.h>
#include <cstdint>

#define TT 16384
#define DD 768
#define HH 3072
#define EE 8
#define HPAD (TT + 128)

// ---------------- scratch globals ------------------------------------------
__device__ int   g_cnt[EE];
__device__ int   g_tok[EE * TT];
__device__ float g_wt [EE * TT];
__device__ int   g_kidx[EE * TT];
__device__ __half g_x16[(size_t)TT * DD];
__device__ __half g_w1t[(size_t)EE * HH * DD];  // [E][H][D] K-major
__device__ __half g_w2t[(size_t)EE * DD * HH];  // [E][D][H] K-major
__device__ __half g_h16[(size_t)EE * HPAD * HH];
__device__ float g_yp[(size_t)TT * 2 * DD];

// ---------------- PTX helpers (base ISA only) -------------------------------
__device__ __forceinline__ uint32_t smem_u32(const void* p) {
    uint32_t a;
    asm("{ .reg .u64 t; cvta.to.shared.u64 t, %1; cvt.u32.u64 %0, t; }"
        : "=r"(a) : "l"(p));
    return a;
}
__device__ __forceinline__ void cpa16(uint32_t dst, const void* src) {
    asm volatile("cp.async.cg.shared.global [%0], [%1], 16;" :: "r"(dst), "l"(src));
}
__device__ __forceinline__ void cpa_commit() {
    asm volatile("cp.async.commit_group;" ::: "memory");
}
template<int N> __device__ __forceinline__ void cpa_wait() {
    asm volatile("cp.async.wait_group %0;" :: "n"(N) : "memory");
}
__device__ __forceinline__ void ldsm4(uint32_t* r, uint32_t addr) {
    asm volatile("ldmatrix.sync.aligned.m8n8.x4.shared.b16 {%0,%1,%2,%3}, [%4];"
                 : "=r"(r[0]), "=r"(r[1]), "=r"(r[2]), "=r"(r[3]) : "r"(addr));
}
__device__ __forceinline__ void mma16816(float* c, const uint32_t* a, const uint32_t* b) {
    asm volatile(
        "mma.sync.aligned.m16n8k16.row.col.f32.f16.f16.f32 "
        "{%0,%1,%2,%3}, {%4,%5,%6,%7}, {%8,%9}, {%0,%1,%2,%3};"
        : "+f"(c[0]), "+f"(c[1]), "+f"(c[2]), "+f"(c[3])
        : "r"(a[0]), "r"(a[1]), "r"(a[2]), "r"(a[3]), "r"(b[0]), "r"(b[1]));
}
__device__ __forceinline__ uint32_t swz(uint32_t off) {
    return off ^ ((off >> 3) & 0x70);
}
__device__ __forceinline__ float gelu_exact(float v) {
    return 0.5f * v * (1.f + erff(v * 0.70710678118654752440f));
}

// ---------------- small kernels --------------------------------------------
__global__ void zero_cnt_kernel() {
    if (threadIdx.x < EE) g_cnt[threadIdx.x] = 0;
}

__global__ __launch_bounds__(256) void convert_x_kernel(const float* __restrict__ x) {
    size_t i = ((size_t)blockIdx.x * 256 + threadIdx.x) * 4;
    float4 v = *(const float4*)(x + i);
    __half2 p0 = __floats2half2_rn(v.x, v.y);
    __half2 p1 = __floats2half2_rn(v.z, v.w);
    uint2 o; o.x = *(uint32_t*)&p0; o.y = *(uint32_t*)&p1;
    *(uint2*)(g_x16 + i) = o;
}

// which=0: w1 [E][D][H] -> [E][H][D]; which=1: w2 [E][H][D] -> [E][D][H]
__global__ __launch_bounds__(256) void transpose_split_kernel(
    const float* __restrict__ in, int which)
{
    int R = which ? HH : DD;
    int C = which ? DD : HH;
    __half* outp = which ? g_w2t : g_w1t;
    __shared__ float tile[32][33];
    int e  = blockIdx.z;
    int r0 = blockIdx.y * 32, c0 = blockIdx.x * 32;
    const float* src = in + (size_t)e * R * C;
    for (int i = threadIdx.y; i < 32; i += 8)
        tile[i][threadIdx.x] = src[(size_t)(r0 + i) * C + c0 + threadIdx.x];
    __syncthreads();
    __half* dst = outp + (size_t)e * R * C;
    for (int i = threadIdx.y; i < 32; i += 8) {
        float v = tile[threadIdx.x][i];
        dst[(size_t)(c0 + i) * R + r0 + threadIdx.x] = __float2half_rn(v);
    }
}

__global__ __launch_bounds__(256) void router_kernel(
    const float* __restrict__ x,
    const float* __restrict__ rw,
    const float* __restrict__ rb)
{
    int gwarp = (blockIdx.x * blockDim.x + threadIdx.x) >> 5;
    int lane  = threadIdx.x & 31;
    if (gwarp >= TT) return;
    const float* xr = x + (size_t)gwarp * DD;

    float acc[EE];
#pragma unroll
    for (int e = 0; e < EE; e++) acc[e] = 0.f;
    for (int d = lane; d < DD; d += 32) {
        float xv = xr[d];
        const float4 w0 = *(const float4*)(rw + (size_t)d * EE);
        const float4 w1 = *(const float4*)(rw + (size_t)d * EE + 4);
        acc[0] += xv * w0.x; acc[1] += xv * w0.y;
        acc[2] += xv * w0.z; acc[3] += xv * w0.w;
        acc[4] += xv * w1.x; acc[5] += xv * w1.y;
        acc[6] += xv * w1.z; acc[7] += xv * w1.w;
    }
#pragma unroll
    for (int off = 16; off; off >>= 1)
#pragma unroll
        for (int e = 0; e < EE; e++)
            acc[e] += __shfl_down_sync(0xffffffffu, acc[e], off);
    if (lane == 0) {
        float lg[EE];
#pragma unroll
        for (int e = 0; e < EE; e++) lg[e] = acc[e] + rb[e];
        int i0 = 0; float v0 = lg[0];
#pragma unroll
        for (int e = 1; e < EE; e++) if (lg[e] > v0) { v0 = lg[e]; i0 = e; }
        int i1 = -1; float v1 = -3.4e38f;
#pragma unroll
        for (int e = 0; e < EE; e++) {
            if (e == i0) continue;
            if (lg[e] > v1) { v1 = lg[e]; i1 = e; }
        }
        float e1 = __expf(v1 - v0);
        float w0 = 1.f / (1.f + e1);
        float w1 = e1 * w0;
        int s0 = atomicAdd(&g_cnt[i0], 1);
        g_tok[i0 * TT + s0] = gwarp; g_wt[i0 * TT + s0] = w0; g_kidx[i0 * TT + s0] = 0;
        int s1 = atomicAdd(&g_cnt[i1], 1);
        g_tok[i1 * TT + s1] = gwarp; g_wt[i1 * TT + s1] = w1; g_kidx[i1 * TT + s1] = 1;
    }
}

// ---------------- fp16 GEMM via mma.sync (tensor pipe) ----------------------
// D[m,n] = sum_k A[m,k]*B[n,k].  CTA: 128x128 tile, 256 thr (8 warps, 4m x 2n),
// warp tile 32m x 64n. K-chunk 64, SW128 K-major smem, cp.async 3-stage.
template<int K_TOT, bool G1>
__global__ void __launch_bounds__(256, 2) gemm_tc_kernel(const float* __restrict__ bias)
{
    constexpr int NK    = K_TOT / 64;
    constexpr int AB    = 128 * 128;      // 16 KB per matrix per stage
    constexpr int STAGE = 2 * AB;         // A, B
    constexpr int NTOT  = G1 ? HH : DD;

    int e   = blockIdx.z;
    int cnt = g_cnt[e];
    int m0  = blockIdx.y * 128;
    if (m0 >= cnt) return;
    int n0  = blockIdx.x * 128;

    extern __shared__ char dynsm[];
    uint32_t dsm = (smem_u32(dynsm) + 1023u) & ~1023u;

    int tid = threadIdx.x, wid = tid >> 5, lane = tid & 31;
    int warp_m = (wid & 3) * 32;
    int warp_n = (wid >> 2) * 64;

    // per-thread load source rows
    const __half* arow;
    {
        int r = tid >> 1;
        if (G1) {
            int gr = m0 + r; if (gr > cnt - 1) gr = cnt - 1;
            int t = g_tok[e * TT + gr];
            arow = g_x16 + (size_t)t * DD;
        } else {
            arow = g_h16 + ((size_t)e * HPAD + m0 + r) * HH;
        }
    }
    const __half* brow = (G1 ? g_w1t : g_w2t) +
        ((size_t)e * NTOT + n0 + (tid >> 1)) * (size_t)K_TOT;

    int lrow = tid >> 1;
    int lseg = (tid & 1) * 4;

    auto load_stage = [&](int s, int k0) {
        uint32_t st = dsm + s * STAGE;
#pragma unroll
        for (int q = 0; q < 4; q++) {
            uint32_t off = swz((uint32_t)(lrow * 128 + (lseg + q) * 16));
            const int koff = (lseg + q) * 8;
            cpa16(st + off,      arow + k0 + koff);
            cpa16(st + AB + off, brow + k0 + koff);
        }
        cpa_commit();
    };

    float acc[2][8][4];
#pragma unroll
    for (int i = 0; i < 2; i++)
#pragma unroll
        for (int j = 0; j < 8; j++)
#pragma unroll
            for (int q = 0; q < 4; q++) acc[i][j][q] = 0.f;

    // ldmatrix per-lane address offsets (within tile, before swizzle)
    int a_r  = (lane & 7) + ((lane >> 3) & 1) * 8;
    int a_c  = (lane >> 4) * 16;
    int b_r  = (lane & 7) + (lane >> 4) * 8;
    int b_c  = ((lane >> 3) & 1) * 16;

    load_stage(0, 0);
    load_stage(1, 64);

    for (int i = 0; i < NK; i++) {
        __syncthreads();
        if (i + 2 < NK) load_stage((i + 2) % 3, (i + 2) * 64);
        if (i < NK - 2)       cpa_wait<2>();
        else if (i == NK - 2) cpa_wait<1>();
        else                  cpa_wait<0>();
        __syncthreads();

        uint32_t st = dsm + (i % 3) * STAGE;
#pragma unroll
        for (int kk = 0; kk < 4; kk++) {
            int c0 = kk * 32;
            uint32_t A[2][4], B[8][2];
#pragma unroll
            for (int mf = 0; mf < 2; mf++) {
                int row = warp_m + mf * 16 + a_r;
                ldsm4(A[mf], st + swz((uint32_t)(row * 128 + c0 + a_c)));
            }
#pragma unroll
            for (int np = 0; np < 4; np++) {
                int row = warp_n + np * 16 + b_r;
                uint32_t r4[4];
                ldsm4(r4, st + AB + swz((uint32_t)(row * 128 + c0 + b_c)));
                B[2 * np][0] = r4[0]; B[2 * np][1] = r4[1];
                B[2 * np + 1][0] = r4[2]; B[2 * np + 1][1] = r4[3];
            }
#pragma unroll
            for (int mf = 0; mf < 2; mf++)
#pragma unroll
                for (int nf = 0; nf < 8; nf++)
                    mma16816(acc[mf][nf], A[mf], B[nf]);
        }
    }

    // ---------------- epilogue ----------------
    int lane4 = lane >> 2;
    int lcol  = (lane & 3) * 2;

#pragma unroll
    for (int mf = 0; mf < 2; mf++) {
#pragma unroll
        for (int h = 0; h < 2; h++) {
            int gr = m0 + warp_m + mf * 16 + h * 8 + lane4;
            if (gr >= cnt) continue;
            if (G1) {
                __half* oh = g_h16 + ((size_t)e * HPAD + gr) * HH;
                const float* bp = bias + (size_t)e * NTOT;
#pragma unroll
                for (int nf = 0; nf < 8; nf++) {
                    int n = n0 + warp_n + nf * 8 + lcol;
                    float v0 = gelu_exact(acc[mf][nf][h * 2 + 0] + bp[n]);
                    float v1 = gelu_exact(acc[mf][nf][h * 2 + 1] + bp[n + 1]);
                    __half2 hp = __floats2half2_rn(v0, v1);
                    *(uint32_t*)&oh[n] = *(uint32_t*)&hp;
                }
            } else {
                int idx = e * TT + gr;
                int   tok = g_tok[idx];
                float wt  = g_wt[idx];
                int   kx  = g_kidx[idx];
                float* orow = g_yp + ((size_t)tok * 2 + kx) * DD;
                const float* bp = bias + (size_t)e * NTOT;
#pragma unroll
                for (int nf = 0; nf < 8; nf++) {
                    int n = n0 + warp_n + nf * 8 + lcol;
                    float2 o;
                    o.x = (acc[mf][nf][h * 2 + 0] + bp[n])     * wt;
                    o.y = (acc[mf][nf][h * 2 + 1] + bp[n + 1]) * wt;
                    *(float2*)(orow + n) = o;
                }
            }
        }
    }
}

// ---------------- residual + LayerNorm --------------------------------------
__device__ __forceinline__ float block_sum256(float v) {
    __shared__ float sh[8];
    int lane = threadIdx.x & 31, w = threadIdx.x >> 5;
#pragma unroll
    for (int o = 16; o; o >>= 1) v += __shfl_down_sync(0xffffffffu, v, o);
    if (lane == 0) sh[w] = v;
    __syncthreads();
    if (threadIdx.x == 0) {
        float s = 0.f;
#pragma unroll
        for (int i = 0; i < 8; i++) s += sh[i];
        sh[0] = s;
    }
    __syncthreads();
    float r = sh[0];
    __syncthreads();
    return r;
}

__global__ __launch_bounds__(256) void ln_kernel(
    const float* __restrict__ x,
    const float* __restrict__ gamma,
    const float* __restrict__ beta,
    float* __restrict__ out)
{
    int t = blockIdx.x;
    const float* xr = x + (size_t)t * DD;
    const float* p0 = g_yp + (size_t)t * 2 * DD;
    const float* p1 = p0 + DD;

    float v[3];
    float s = 0.f;
#pragma unroll
    for (int i = 0; i < 3; i++) {
        int d = threadIdx.x + i * 256;
        v[i] = xr[d] + p0[d] + p1[d];
        s += v[i];
    }
    s = block_sum256(s);
    float mu = s * (1.f / (float)DD);
    float q = 0.f;
#pragma unroll
    for (int i = 0; i < 3; i++) { float dl = v[i] - mu; q += dl * dl; }
    q = block_sum256(q);
    float rstd = rsqrtf(q * (1.f / (float)DD) + 1e-5f);
#pragma unroll
    for (int i = 0; i < 3; i++) {
        int d = threadIdx.x + i * 256;
        out[(size_t)t * DD + d] = (v[i] - mu) * rstd * gamma[d] + beta[d];
    }
}

// ---------------------------------------------------------------------------
extern "C" void kernel_launch(void* const* d_in, const int* in_sizes, int n_in,
                              void* d_out, int out_size)
{
    (void)in_sizes; (void)n_in; (void)out_size;
    const float* x   = (const float*)d_in[0];
    const float* rw  = (const float*)d_in[1];
    const float* rb  = (const float*)d_in[2];
    const float* w1  = (const float*)d_in[3];
    const float* b1  = (const float*)d_in[4];
    const float* w2  = (const float*)d_in[5];
    const float* b2  = (const float*)d_in[6];
    const float* gam = (const float*)d_in[7];
    const float* bet = (const float*)d_in[8];
    float* out = (float*)d_out;

    const int SMEM_SZ = 3 * 2 * 128 * 128 + 1024;   // 3 stages x 32KB + pad
    cudaFuncSetAttribute(gemm_tc_kernel<DD, true>,
                         cudaFuncAttributeMaxDynamicSharedMemorySize, SMEM_SZ);
    cudaFuncSetAttribute(gemm_tc_kernel<HH, false>,
                         cudaFuncAttributeMaxDynamicSharedMemorySize, SMEM_SZ);

    zero_cnt_kernel<<<1, 32>>>();
    router_kernel<<<TT / 8, 256>>>(x, rw, rb);
    convert_x_kernel<<<(TT * DD) / (256 * 4), 256>>>(x);
    transpose_split_kernel<<<dim3(HH / 32, DD / 32, EE), dim3(32, 8)>>>(w1, 0);
    transpose_split_kernel<<<dim3(DD / 32, HH / 32, EE), dim3(32, 8)>>>(w2, 1);
    gemm_tc_kernel<DD, true><<<dim3(HH / 128, TT / 128, EE), 256, SMEM_SZ>>>(b1);
    gemm_tc_kernel<HH, false><<<dim3(DD / 128, TT / 128, EE), 256, SMEM_SZ>>>(b2);
    ln_kernel<<<TT, 256>>>(x, gam, bet, out);
}